// round 9
// baseline (speedup 1.0000x reference)
#include <cuda_runtime.h>
#include <cuda_fp16.h>
#include <cstdint>

#define KD 4096   // input features
#define ND 4096   // output features
#define MD 8192   // rows of x

// Static device scratch.
static __device__ __half g_W[(size_t)ND * KD];  // dequantized Wt[n][k], 32MB
static __device__ __half g_X[(size_t)MD * KD];  // x fp16, 64MB

// ---------------------------------------------------------------------------
// Convert x: fp32 (holding fp16 values) -> fp16. 8 elems/thread.
// ---------------------------------------------------------------------------
__global__ void convert_x_kernel(const float* __restrict__ x) {
    size_t i = ((size_t)blockIdx.x * blockDim.x + threadIdx.x) * 8;
    float4 a = *reinterpret_cast<const float4*>(x + i);
    float4 b = *reinterpret_cast<const float4*>(x + i + 4);
    __half h[8];
    h[0] = __float2half_rn(a.x); h[1] = __float2half_rn(a.y);
    h[2] = __float2half_rn(a.z); h[3] = __float2half_rn(a.w);
    h[4] = __float2half_rn(b.x); h[5] = __float2half_rn(b.y);
    h[6] = __float2half_rn(b.z); h[7] = __float2half_rn(b.w);
    *reinterpret_cast<uint4*>(&g_X[i]) = *reinterpret_cast<const uint4*>(h);
}

// ---------------------------------------------------------------------------
// Dequant: int4 -> fp16 Wt[n][k], fp16 arithmetic matching the reference.
// ---------------------------------------------------------------------------
__global__ void dequant_kernel(const int* __restrict__ qw,
                               const float* __restrict__ scales,
                               const float* __restrict__ qzeros) {
    int idx = blockIdx.x * blockDim.x + threadIdx.x;
    int n = idx >> 9;
    int r = idx & 511;
    uint32_t q = (uint32_t)qw[r * ND + n];
    int g = r >> 3;
    __half hs = __float2half_rn(scales[g * ND + n]);
    __half hz = __float2half_rn(qzeros[g * ND + n]);
    __half hzs = __hmul(hz, hs);
    __half h[8];
#pragma unroll
    for (int i = 0; i < 8; i++) {
        __half hw = __float2half_rn((float)((q >> (4 * i)) & 15u));
        h[i] = __hsub(__hmul(hs, hw), hzs);
    }
    *reinterpret_cast<uint4*>(&g_W[(size_t)n * KD + r * 8]) =
        *reinterpret_cast<const uint4*>(h);
}

// ---------------------------------------------------------------------------
// GEMM: C = X * Wt^T + bias. BM=BN=128, BK=32, 128 threads = 4 warps (2x2),
// warp tile 64x64. 5-stage cp.async pipeline (4 chunks of lookahead).
// Register double-buffered fragments: both k16 sub-steps' LDSMs issue before
// the MMAs, hiding LDSM latency under the MMA stream. 2 CTAs/SM.
// ---------------------------------------------------------------------------
constexpr int BM = 128, BN = 128, BK = 32, STAGES = 5;
constexpr int LDS_ = BK + 8;                            // 40 halfs per row
constexpr int SMEM_HALFS = STAGES * (BM + BN) * LDS_;   // 51200 halfs = 100KB

__device__ __forceinline__ void cp16(uint32_t sdst, const void* g) {
    asm volatile("cp.async.cg.shared.global [%0], [%1], 16;\n" :: "r"(sdst), "l"(g));
}

__global__ void __launch_bounds__(128, 2)
gemm_kernel(const float* __restrict__ bias,
            float* __restrict__ C) {
    extern __shared__ __half sm[];
    __half* As = sm;
    __half* Bs = sm + STAGES * BM * LDS_;

    const int tid  = threadIdx.x;
    const int lane = tid & 31;
    const int warp = tid >> 5;
    const int wm = warp & 1;
    const int wn = warp >> 1;
    const int bm = blockIdx.y * BM;
    const int bn = blockIdx.x * BN;

    const uint32_t as_base = (uint32_t)__cvta_generic_to_shared(As);
    const uint32_t bs_base = (uint32_t)__cvta_generic_to_shared(Bs);

    float acc[4][8][4];
#pragma unroll
    for (int i = 0; i < 4; i++)
#pragma unroll
        for (int j = 0; j < 8; j++)
#pragma unroll
            for (int t = 0; t < 4; t++) acc[i][j][t] = 0.f;

    // 1024 16B-chunks per stage (A:512, B:512); 8 per thread.
    auto load_stage = [&](int kt, int s) {
        int k0 = kt * BK;
#pragma unroll
        for (int i = 0; i < 4; i++) {
            int cid = i * 128 + tid;       // 0..511
            int row = cid >> 2;
            int ch  = cid & 3;
            cp16(as_base + (uint32_t)((s * BM + row) * LDS_ + ch * 8) * 2,
                 g_X + (size_t)(bm + row) * KD + k0 + ch * 8);
        }
#pragma unroll
        for (int i = 0; i < 4; i++) {
            int cid = i * 128 + tid;       // 0..511
            int row = cid >> 2;
            int ch  = cid & 3;
            cp16(bs_base + (uint32_t)((s * BN + row) * LDS_ + ch * 8) * 2,
                 g_W + (size_t)(bn + row) * KD + k0 + ch * 8);
        }
        asm volatile("cp.async.commit_group;\n");
    };

    const int ar = wm * 64 + (lane & 15);
    const int ac0 = (lane >> 4) << 3;
    const int br = wn * 64 + ((lane >> 4) << 3) + (lane & 7);
    const int bc0 = ((lane >> 3) & 1) << 3;

    uint32_t a[2][4][4];
    uint32_t b[2][8][2];

    auto load_frag = [&](int s, int ks, int bufi) {
        int ac = ks * 16 + ac0;
        int bc = ks * 16 + bc0;
#pragma unroll
        for (int mi = 0; mi < 4; mi++) {
            uint32_t addr = as_base +
                (uint32_t)((s * BM + ar + mi * 16) * LDS_ + ac) * 2;
            asm volatile(
                "ldmatrix.sync.aligned.m8n8.x4.shared.b16 {%0,%1,%2,%3}, [%4];\n"
                : "=r"(a[bufi][mi][0]), "=r"(a[bufi][mi][1]),
                  "=r"(a[bufi][mi][2]), "=r"(a[bufi][mi][3])
                : "r"(addr));
        }
#pragma unroll
        for (int nh = 0; nh < 4; nh++) {
            uint32_t addr = bs_base +
                (uint32_t)((s * BN + br + nh * 16) * LDS_ + bc) * 2;
            asm volatile(
                "ldmatrix.sync.aligned.m8n8.x4.shared.b16 {%0,%1,%2,%3}, [%4];\n"
                : "=r"(b[bufi][nh * 2][0]), "=r"(b[bufi][nh * 2][1]),
                  "=r"(b[bufi][nh * 2 + 1][0]), "=r"(b[bufi][nh * 2 + 1][1])
                : "r"(addr));
        }
    };

    auto mma_frag = [&](int bufi) {
#pragma unroll
        for (int mi = 0; mi < 4; mi++)
#pragma unroll
            for (int ni = 0; ni < 8; ni++) {
                asm volatile(
                    "mma.sync.aligned.m16n8k16.row.col.f32.f16.f16.f32 "
                    "{%0,%1,%2,%3}, {%4,%5,%6,%7}, {%8,%9}, {%0,%1,%2,%3};\n"
                    : "+f"(acc[mi][ni][0]), "+f"(acc[mi][ni][1]),
                      "+f"(acc[mi][ni][2]), "+f"(acc[mi][ni][3])
                    : "r"(a[bufi][mi][0]), "r"(a[bufi][mi][1]),
                      "r"(a[bufi][mi][2]), "r"(a[bufi][mi][3]),
                      "r"(b[bufi][ni][0]), "r"(b[bufi][ni][1]));
            }
    };

    const int KT = KD / BK;   // 128
#pragma unroll
    for (int s = 0; s < STAGES - 1; s++) load_stage(s, s);

    int cs = 0;                         // stage of chunk kt
    int ls = STAGES - 1;                // stage of chunk kt+STAGES-1
    for (int kt = 0; kt < KT; kt++) {
        asm volatile("cp.async.wait_group %0;\n" :: "n"(STAGES - 2));
        __syncthreads();
        int nk = kt + STAGES - 1;
        if (nk < KT) load_stage(nk, ls);
        else         asm volatile("cp.async.commit_group;\n");

        // LDSM both sub-steps up front, then both MMA batches.
        load_frag(cs, 0, 0);
        load_frag(cs, 1, 1);
        mma_frag(0);
        mma_frag(1);

        if (++cs == STAGES) cs = 0;
        if (++ls == STAGES) ls = 0;
    }

    // Epilogue: fp16(acc) + fp16(bias), store fp32 (mirrors reference rounding).
    const int group = lane >> 2, tig = lane & 3;
#pragma unroll
    for (int mi = 0; mi < 4; mi++) {
        int row = bm + wm * 64 + mi * 16 + group;
#pragma unroll
        for (int ni = 0; ni < 8; ni++) {
            int col = bn + wn * 64 + ni * 8 + tig * 2;
            float2 bb = *reinterpret_cast<const float2*>(&bias[col]);
            __half hb0 = __float2half_rn(bb.x);
            __half hb1 = __float2half_rn(bb.y);
            float2 r0, r1;
            r0.x = __half2float(__hadd(__float2half_rn(acc[mi][ni][0]), hb0));
            r0.y = __half2float(__hadd(__float2half_rn(acc[mi][ni][1]), hb1));
            r1.x = __half2float(__hadd(__float2half_rn(acc[mi][ni][2]), hb0));
            r1.y = __half2float(__hadd(__float2half_rn(acc[mi][ni][3]), hb1));
            *reinterpret_cast<float2*>(&C[(size_t)row * ND + col]) = r0;
            *reinterpret_cast<float2*>(&C[(size_t)(row + 8) * ND + col]) = r1;
        }
    }
}

// ---------------------------------------------------------------------------
extern "C" void kernel_launch(void* const* d_in, const int* in_sizes, int n_in,
                              void* d_out, int out_size) {
    const float* x      = (const float*)d_in[0];
    const int*   qw     = (const int*)d_in[1];
    const float* scales = (const float*)d_in[2];
    const float* qzeros = (const float*)d_in[3];
    const float* bias   = (const float*)d_in[4];

    convert_x_kernel<<<(MD * (size_t)KD) / (8 * 256), 256>>>(x);
    dequant_kernel<<<(512 * ND) / 256, 256>>>(qw, scales, qzeros);

    size_t smem = (size_t)SMEM_HALFS * sizeof(__half);   // 100KB
    cudaFuncSetAttribute(gemm_kernel,
                         cudaFuncAttributeMaxDynamicSharedMemorySize, (int)smem);
    dim3 grid(ND / BN, MD / BM);   // (32, 64)
    gemm_kernel<<<grid, 128, smem>>>(bias, (float*)d_out);
}

// round 10
// speedup vs baseline: 1.0052x; 1.0052x over previous
#include <cuda_runtime.h>
#include <cuda_fp16.h>
#include <cstdint>

#define KD 4096   // input features
#define ND 4096   // output features
#define MD 8192   // rows of x

// Static device scratch.
static __device__ __half g_W[(size_t)ND * KD];  // dequantized Wt[n][k], 32MB
static __device__ __half g_X[(size_t)MD * KD];  // x fp16, 64MB

// ---------------------------------------------------------------------------
// Convert x: fp32 (holding fp16 values) -> fp16. 8 elems/thread.
// ---------------------------------------------------------------------------
__global__ void convert_x_kernel(const float* __restrict__ x) {
    size_t i = ((size_t)blockIdx.x * blockDim.x + threadIdx.x) * 8;
    float4 a = *reinterpret_cast<const float4*>(x + i);
    float4 b = *reinterpret_cast<const float4*>(x + i + 4);
    __half h[8];
    h[0] = __float2half_rn(a.x); h[1] = __float2half_rn(a.y);
    h[2] = __float2half_rn(a.z); h[3] = __float2half_rn(a.w);
    h[4] = __float2half_rn(b.x); h[5] = __float2half_rn(b.y);
    h[6] = __float2half_rn(b.z); h[7] = __float2half_rn(b.w);
    *reinterpret_cast<uint4*>(&g_X[i]) = *reinterpret_cast<const uint4*>(h);
}

// ---------------------------------------------------------------------------
// Dequant with coalesced reads: block = 128n x 128k tile (16 qweight rows).
// Threads read qw with consecutive n (coalesced), dequant in regs, transpose
// through smem (272B row stride -> conflict-free 16B STS), write g_W with
// 32B-sector-aligned coalesced stores along k.
// ---------------------------------------------------------------------------
constexpr int DQ_PADK = 136;   // 128 k halfs + 8 pad -> 272B rows (odd 16B mult)

__global__ void __launch_bounds__(256)
dequant_kernel(const int* __restrict__ qw,
               const float* __restrict__ scales,
               const float* __restrict__ qzeros) {
    __shared__ __half tile[128 * DQ_PADK];   // 34KB

    const int tid = threadIdx.x;
    const int n0 = (blockIdx.x & 31) * 128;      // 32 n-tiles
    const int r0 = (blockIdx.x >> 5) * 16;       // 32 r-tiles (16 rows each)

    const int n_loc = tid & 127;                  // 0..127
    const int r_hi  = tid >> 7;                   // 0..1
    const int n = n0 + n_loc;

    // Each thread handles 8 qweight rows: r = r0 + r_hi*8 + p, p=0..7.
    // Groups: g = (r0 + r_hi*8)/8 ... each 8-row span is one scale group
    // (group = r/8 since groupsize 64 = 8 rows).
#pragma unroll
    for (int p = 0; p < 8; p++) {
        int r = r0 + r_hi * 8 + p;
        int g = r >> 3;
        uint32_t q = (uint32_t)qw[r * ND + n];            // coalesced (512B/warp)
        __half hs = __float2half_rn(scales[g * ND + n]);  // coalesced
        __half hz = __float2half_rn(qzeros[g * ND + n]);
        __half hzs = __hmul(hz, hs);
        __half h[8];
#pragma unroll
        for (int i = 0; i < 8; i++) {
            __half hw = __float2half_rn((float)((q >> (4 * i)) & 15u));
            h[i] = __hsub(__hmul(hs, hw), hzs);
        }
        // STS 16B at [n_loc][(r - r0)*8]
        *reinterpret_cast<uint4*>(&tile[n_loc * DQ_PADK + (r_hi * 8 + p) * 8]) =
            *reinterpret_cast<const uint4*>(h);
    }
    __syncthreads();

    // Write out: 128n x 128k halfs = 32KB; 16B per store, 8 passes.
    // thread t -> n = t>>1, chunk c = (t&1) + pass*2  (chunks of 8 halfs)
    const int wn = tid >> 1;
    const int k0 = r0 * 8;
#pragma unroll
    for (int pass = 0; pass < 8; pass++) {
        int c = (tid & 1) + pass * 2;
        uint4 v = *reinterpret_cast<const uint4*>(&tile[wn * DQ_PADK + c * 8]);
        *reinterpret_cast<uint4*>(&g_W[(size_t)(n0 + wn) * KD + k0 + c * 8]) = v;
    }
}

// ---------------------------------------------------------------------------
// GEMM: C = X * Wt^T + bias. BM=BN=128, BK=32, 128 threads = 4 warps (2x2),
// warp tile 64x64. 5-stage cp.async pipeline (4 chunks of lookahead).
// Single fragment buffer (R8 proven layout). 2 CTAs/SM.
// ---------------------------------------------------------------------------
constexpr int BM = 128, BN = 128, BK = 32, STAGES = 5;
constexpr int LDS_ = BK + 8;                            // 40 halfs per row
constexpr int SMEM_HALFS = STAGES * (BM + BN) * LDS_;   // 51200 halfs = 100KB

__device__ __forceinline__ void cp16(uint32_t sdst, const void* g) {
    asm volatile("cp.async.cg.shared.global [%0], [%1], 16;\n" :: "r"(sdst), "l"(g));
}

__global__ void __launch_bounds__(128, 2)
gemm_kernel(const float* __restrict__ bias,
            float* __restrict__ C) {
    extern __shared__ __half sm[];
    __half* As = sm;
    __half* Bs = sm + STAGES * BM * LDS_;

    const int tid  = threadIdx.x;
    const int lane = tid & 31;
    const int warp = tid >> 5;
    const int wm = warp & 1;
    const int wn = warp >> 1;
    const int bm = blockIdx.y * BM;
    const int bn = blockIdx.x * BN;

    const uint32_t as_base = (uint32_t)__cvta_generic_to_shared(As);
    const uint32_t bs_base = (uint32_t)__cvta_generic_to_shared(Bs);

    float acc[4][8][4];
#pragma unroll
    for (int i = 0; i < 4; i++)
#pragma unroll
        for (int j = 0; j < 8; j++)
#pragma unroll
            for (int t = 0; t < 4; t++) acc[i][j][t] = 0.f;

    // 1024 16B-chunks per stage (A:512, B:512); 8 per thread.
    auto load_stage = [&](int kt, int s) {
        int k0 = kt * BK;
#pragma unroll
        for (int i = 0; i < 4; i++) {
            int cid = i * 128 + tid;       // 0..511
            int row = cid >> 2;
            int ch  = cid & 3;
            cp16(as_base + (uint32_t)((s * BM + row) * LDS_ + ch * 8) * 2,
                 g_X + (size_t)(bm + row) * KD + k0 + ch * 8);
        }
#pragma unroll
        for (int i = 0; i < 4; i++) {
            int cid = i * 128 + tid;       // 0..511
            int row = cid >> 2;
            int ch  = cid & 3;
            cp16(bs_base + (uint32_t)((s * BN + row) * LDS_ + ch * 8) * 2,
                 g_W + (size_t)(bn + row) * KD + k0 + ch * 8);
        }
        asm volatile("cp.async.commit_group;\n");
    };

    auto compute_stage = [&](int s) {
#pragma unroll
        for (int ks = 0; ks < 2; ks++) {   // two k16 steps per BK=32
            uint32_t a[4][4];
            uint32_t b[8][2];
            int ar = wm * 64 + (lane & 15);
            int ac = ks * 16 + ((lane >> 4) << 3);
#pragma unroll
            for (int mi = 0; mi < 4; mi++) {
                uint32_t addr = as_base +
                    (uint32_t)((s * BM + ar + mi * 16) * LDS_ + ac) * 2;
                asm volatile(
                    "ldmatrix.sync.aligned.m8n8.x4.shared.b16 {%0,%1,%2,%3}, [%4];\n"
                    : "=r"(a[mi][0]), "=r"(a[mi][1]), "=r"(a[mi][2]), "=r"(a[mi][3])
                    : "r"(addr));
            }
            int br = wn * 64 + ((lane >> 4) << 3) + (lane & 7);
            int bc = ks * 16 + (((lane >> 3) & 1) << 3);
#pragma unroll
            for (int nh = 0; nh < 4; nh++) {
                uint32_t addr = bs_base +
                    (uint32_t)((s * BN + br + nh * 16) * LDS_ + bc) * 2;
                asm volatile(
                    "ldmatrix.sync.aligned.m8n8.x4.shared.b16 {%0,%1,%2,%3}, [%4];\n"
                    : "=r"(b[nh * 2][0]), "=r"(b[nh * 2][1]),
                      "=r"(b[nh * 2 + 1][0]), "=r"(b[nh * 2 + 1][1])
                    : "r"(addr));
            }
#pragma unroll
            for (int mi = 0; mi < 4; mi++)
#pragma unroll
                for (int ni = 0; ni < 8; ni++) {
                    asm volatile(
                        "mma.sync.aligned.m16n8k16.row.col.f32.f16.f16.f32 "
                        "{%0,%1,%2,%3}, {%4,%5,%6,%7}, {%8,%9}, {%0,%1,%2,%3};\n"
                        : "+f"(acc[mi][ni][0]), "+f"(acc[mi][ni][1]),
                          "+f"(acc[mi][ni][2]), "+f"(acc[mi][ni][3])
                        : "r"(a[mi][0]), "r"(a[mi][1]), "r"(a[mi][2]), "r"(a[mi][3]),
                          "r"(b[ni][0]), "r"(b[ni][1]));
                }
        }
    };

    const int KT = KD / BK;   // 128
#pragma unroll
    for (int s = 0; s < STAGES - 1; s++) load_stage(s, s);

    int cs = 0;                         // stage of chunk kt
    int ls = STAGES - 1;                // stage of chunk kt+STAGES-1
    for (int kt = 0; kt < KT; kt++) {
        asm volatile("cp.async.wait_group %0;\n" :: "n"(STAGES - 2));
        __syncthreads();
        int nk = kt + STAGES - 1;
        if (nk < KT) load_stage(nk, ls);
        else         asm volatile("cp.async.commit_group;\n");
        compute_stage(cs);
        if (++cs == STAGES) cs = 0;
        if (++ls == STAGES) ls = 0;
    }

    // Epilogue: fp16(acc) + fp16(bias), store fp32 (mirrors reference rounding).
    const int group = lane >> 2, tig = lane & 3;
#pragma unroll
    for (int mi = 0; mi < 4; mi++) {
        int row = bm + wm * 64 + mi * 16 + group;
#pragma unroll
        for (int ni = 0; ni < 8; ni++) {
            int col = bn + wn * 64 + ni * 8 + tig * 2;
            float2 bb = *reinterpret_cast<const float2*>(&bias[col]);
            __half hb0 = __float2half_rn(bb.x);
            __half hb1 = __float2half_rn(bb.y);
            float2 r0, r1;
            r0.x = __half2float(__hadd(__float2half_rn(acc[mi][ni][0]), hb0));
            r0.y = __half2float(__hadd(__float2half_rn(acc[mi][ni][1]), hb1));
            r1.x = __half2float(__hadd(__float2half_rn(acc[mi][ni][2]), hb0));
            r1.y = __half2float(__hadd(__float2half_rn(acc[mi][ni][3]), hb1));
            *reinterpret_cast<float2*>(&C[(size_t)row * ND + col]) = r0;
            *reinterpret_cast<float2*>(&C[(size_t)(row + 8) * ND + col]) = r1;
        }
    }
}

// ---------------------------------------------------------------------------
extern "C" void kernel_launch(void* const* d_in, const int* in_sizes, int n_in,
                              void* d_out, int out_size) {
    const float* x      = (const float*)d_in[0];
    const int*   qw     = (const int*)d_in[1];
    const float* scales = (const float*)d_in[2];
    const float* qzeros = (const float*)d_in[3];
    const float* bias   = (const float*)d_in[4];

    convert_x_kernel<<<(MD * (size_t)KD) / (8 * 256), 256>>>(x);
    // 32 n-tiles x 32 r-tiles = 1024 blocks, 256 threads
    dequant_kernel<<<1024, 256>>>(qw, scales, qzeros);

    size_t smem = (size_t)SMEM_HALFS * sizeof(__half);   // 100KB
    cudaFuncSetAttribute(gemm_kernel,
                         cudaFuncAttributeMaxDynamicSharedMemorySize, (int)smem);
    dim3 grid(ND / BN, MD / BM);   // (32, 64)
    gemm_kernel<<<grid, 128, smem>>>(bias, (float*)d_out);
}